// round 13
// baseline (speedup 1.0000x reference)
#include <cuda_runtime.h>

// PSRoIAlign: feat [B=4, C=784, H=80, W=80] f32, rois [N=512, 5] f32
// out [N, 16, 7, 7] f32. Channel of output element = r = co*49 + ph*7 + pw.
//
// R13: block-shared geometry. A 256-thread block covers outputs
// [blk*256, blk*256+256) which span <=2 rois. Threads 0..27 build per-roi
// geometry tables in smem (x: W[8] weight vector + window base; y: row
// offsets + y-weights), one __syncthreads, then all threads run a lean main
// path: index math + broadcast LDS + 4-6 LDG.128 (2 sequential rounds,
// <=4 live float4) + dot8. Low regs -> high occupancy (launch_bounds 256,7).

#define PH 7
#define PW 7
#define HH 80
#define WW 80
#define CC 784
#define PLANE (HH * WW)
#define OPR (16 * PH * PW)    // outputs per roi = 784

__device__ __forceinline__ float dot8(float4 lo, float4 hi,
                                      float4 Wl, float4 Wh) {
    float s = lo.x * Wl.x;
    s = fmaf(lo.y, Wl.y, s);
    s = fmaf(lo.z, Wl.z, s);
    s = fmaf(lo.w, Wl.w, s);
    s = fmaf(hi.x, Wh.x, s);
    s = fmaf(hi.y, Wh.y, s);
    s = fmaf(hi.z, Wh.z, s);
    s = fmaf(hi.w, Wh.w, s);
    return s;
}

__global__ void __launch_bounds__(256, 7)
psroi_align_kernel(const float* __restrict__ feat,
                   const float* __restrict__ rois,
                   float* __restrict__ out,
                   int nRois)
{
    __shared__ float4 sWlo[2][PW];
    __shared__ float4 sWhi[2][PW];
    __shared__ int    sXA [2][PW];    // window base xa
    __shared__ int4   sOff[2][PH];    // planeBase + {y0,y1i}*WW for sy=0,1
    __shared__ float4 sWy [2][PH];    // {wA0, wB0, wA1, wB1}

    int base = blockIdx.x * 256;
    int n0   = base / OPR;            // first roi this block touches

    int tid = threadIdx.x;

    // ---- threads 0..27 build geometry tables (2 roi slots x 14 entries) ----
    if (tid < 28) {
        int slot = tid >> 4;          // 0 for tid<16... use /14 layout instead
        slot = tid / 14;
        int e = tid - slot * 14;      // 0..13
        int n = min(n0 + slot, nRois - 1);

        const float* roi = rois + n * 5;
        int   b   = (int)roi[0];
        float rx1 = roi[1] * (float)WW;
        float ry1 = roi[2] * (float)HH;
        float rx2 = roi[3] * (float)WW;
        float ry2 = roi[4] * (float)HH;

        float roi_h = fmaxf(ry2 - ry1, 0.1f);
        float roi_w = fmaxf(rx2 - rx1, 0.1f);
        float bin_h = roi_h * (1.0f / PH);
        float bin_w = roi_w * (1.0f / PW);

        if (e < PW) {
            // ---- x entry for pw = e ----
            int pw = e;
            float xs0 = rx1 + (float)pw * bin_w + 0.25f * bin_w;
            float xs1 = xs0 + 0.5f * bin_w;
            float mx0 = (xs0 >= -1.0f && xs0 <= (float)WW) ? 1.0f : 0.0f;
            float mx1 = (xs1 >= -1.0f && xs1 <= (float)WW) ? 1.0f : 0.0f;
            float xc0 = fminf(fmaxf(xs0, 0.0f), (float)(WW - 1));
            float xc1 = fminf(fmaxf(xs1, 0.0f), (float)(WW - 1));
            int x00 = (int)floorf(xc0);
            int x01 = (int)floorf(xc1);
            int x10 = min(x00 + 1, WW - 1);
            int x11 = min(x01 + 1, WW - 1);
            float lx0 = xc0 - (float)x00, hx0 = 1.0f - lx0;
            float lx1 = xc1 - (float)x01, hx1 = 1.0f - lx1;

            int xa  = x00 & ~3;
            int o00 = x00 - xa;
            int o01 = x10 - xa;
            int o10 = x01 - xa;
            int o11 = x11 - xa;

            float c0 = 0.25f * mx0 * hx0, c1 = 0.25f * mx0 * lx0;
            float c2 = 0.25f * mx1 * hx1, c3 = 0.25f * mx1 * lx1;
            float W[8];
            #pragma unroll
            for (int k = 0; k < 8; ++k) {
                float w = (o00 == k) ? c0 : 0.0f;
                w += (o01 == k) ? c1 : 0.0f;
                w += (o10 == k) ? c2 : 0.0f;
                w += (o11 == k) ? c3 : 0.0f;
                W[k] = w;
            }
            sWlo[slot][pw] = make_float4(W[0], W[1], W[2], W[3]);
            sWhi[slot][pw] = make_float4(W[4], W[5], W[6], W[7]);
            sXA [slot][pw] = xa;
        } else {
            // ---- y entry for ph = e - 7 ----
            int ph = e - PW;
            int planeBase = b * (CC * PLANE);
            float ybase = ry1 + (float)ph * bin_h;
            int   offs[4];
            float wy[4];
            #pragma unroll
            for (int sy = 0; sy < 2; ++sy) {
                float ys = ybase + ((float)sy * 0.5f + 0.25f) * bin_h;
                float my = (ys >= -1.0f && ys <= (float)HH) ? 1.0f : 0.0f;
                float yc = fminf(fmaxf(ys, 0.0f), (float)(HH - 1));
                int y0  = (int)floorf(yc);
                int y1i = min(y0 + 1, HH - 1);
                float ly = yc - (float)y0;
                offs[sy * 2 + 0] = planeBase + y0  * WW;
                offs[sy * 2 + 1] = planeBase + y1i * WW;
                wy[sy * 2 + 0] = my * (1.0f - ly);
                wy[sy * 2 + 1] = my * ly;
            }
            sOff[slot][ph] = make_int4(offs[0], offs[1], offs[2], offs[3]);
            sWy [slot][ph] = make_float4(wy[0], wy[1], wy[2], wy[3]);
        }
    }
    __syncthreads();

    // ---- main path: one output per thread ----
    int p = base + tid;
    int n = p / OPR;
    int slot = n - n0;                 // 0 or 1
    int r = p - n * OPR;               // channel index
    int pw = r % PW;
    int ph = (r / PW) % PH;

    int    xa   = sXA [slot][pw];
    float4 Wl   = sWlo[slot][pw];
    float4 Wh   = sWhi[slot][pw];
    int4   offs = sOff[slot][ph];
    float4 wy   = sWy [slot][ph];

    int cbase = r * PLANE + xa;

    const float* pA0 = feat + (offs.x + cbase);
    const float* pB0 = feat + (offs.y + cbase);
    const float* pA1 = feat + (offs.z + cbase);
    const float* pB1 = feat + (offs.w + cbase);

    // need_hi iff any of W[4..7] nonzero
    bool need_hi = (Wh.x != 0.0f) | (Wh.y != 0.0f) | (Wh.z != 0.0f) | (Wh.w != 0.0f);
    float4 zero = make_float4(0.f, 0.f, 0.f, 0.f);
    float acc;

    // round sy = 0
    {
        float4 Alo = __ldg((const float4*)pA0);
        float4 Blo = __ldg((const float4*)pB0);
        float4 Ahi = zero, Bhi = zero;
        if (need_hi) {
            Ahi = __ldg((const float4*)(pA0 + 4));
            Bhi = __ldg((const float4*)(pB0 + 4));
        }
        acc = wy.x * dot8(Alo, Ahi, Wl, Wh);
        acc = fmaf(wy.y, dot8(Blo, Bhi, Wl, Wh), acc);
    }
    // round sy = 1
    {
        float4 Alo = __ldg((const float4*)pA1);
        float4 Blo = __ldg((const float4*)pB1);
        float4 Ahi = zero, Bhi = zero;
        if (need_hi) {
            Ahi = __ldg((const float4*)(pA1 + 4));
            Bhi = __ldg((const float4*)(pB1 + 4));
        }
        acc = fmaf(wy.z, dot8(Alo, Ahi, Wl, Wh), acc);
        acc = fmaf(wy.w, dot8(Blo, Bhi, Wl, Wh), acc);
    }

    out[p] = acc;
}

extern "C" void kernel_launch(void* const* d_in, const int* in_sizes, int n_in,
                              void* d_out, int out_size)
{
    const float* feat = (const float*)d_in[0];
    const float* rois = (const float*)d_in[1];
    float* out = (float*)d_out;

    int N = in_sizes[1] / 5;            // 512 rois
    int total = N * OPR;                // 401408 outputs, divisible by 256
    int blocks = total / 256;           // 1568

    psroi_align_kernel<<<blocks, 256>>>(feat, rois, out, N);
}

// round 15
// speedup vs baseline: 1.2018x; 1.2018x over previous
#include <cuda_runtime.h>

// PSRoIAlign: feat [B=4, C=784, H=80, W=80] f32, rois [N=512, 5] f32
// out [N, 16, 7, 7] f32. Channel of output element = r = co*49 + ph*7 + pw.
//
// R14 = R5 structure + row dedup. The 4 bilinear rows of both sy samples
// collapse into <=4 distinct rows yb..yb+3 with a y-weight vector Wy
// (separable since x-weights are shared across sy). Rows 2,3 are loaded only
// when their weight is nonzero -> expected ~3 row loads instead of 4
// (~25% fewer LDG.128 = fewer L1 wavefronts, the measured bottleneck).

#define PH 7
#define PW 7
#define HH 80
#define WW 80
#define CC 784

__device__ __forceinline__ float dot8(float4 lo, float4 hi, const float* W) {
    float s = lo.x * W[0];
    s = fmaf(lo.y, W[1], s);
    s = fmaf(lo.z, W[2], s);
    s = fmaf(lo.w, W[3], s);
    s = fmaf(hi.x, W[4], s);
    s = fmaf(hi.y, W[5], s);
    s = fmaf(hi.z, W[6], s);
    s = fmaf(hi.w, W[7], s);
    return s;
}

__global__ void __launch_bounds__(256, 5)
psroi_align_kernel(const float* __restrict__ feat,
                   const float* __restrict__ rois,
                   float* __restrict__ out,
                   int total)
{
    int tid = blockIdx.x * blockDim.x + threadIdx.x;
    if (tid >= total) return;

    int n = tid / (PH * PW * 16);
    int r = tid - n * (PH * PW * 16);      // channel index
    int pw = r % PW;
    int ph = (r / PW) % PH;

    const float* roi = rois + n * 5;
    int   b   = (int)roi[0];
    float rx1 = roi[1] * (float)WW;
    float ry1 = roi[2] * (float)HH;
    float rx2 = roi[3] * (float)WW;
    float ry2 = roi[4] * (float)HH;

    float roi_h = fmaxf(ry2 - ry1, 0.1f);
    float roi_w = fmaxf(rx2 - rx1, 0.1f);
    float bin_h = roi_h * (1.0f / PH);
    float bin_w = roi_w * (1.0f / PW);

    const float* __restrict__ f = feat + ((size_t)b * CC + (size_t)r) * (HH * WW);

    // ---- x geometry -> 8-wide tap weight vector Wx (masks + 1/4 folded) ----
    float xs0 = rx1 + (float)pw * bin_w + 0.25f * bin_w;
    float xs1 = xs0 + 0.5f * bin_w;
    float mx0 = (xs0 >= -1.0f && xs0 <= (float)WW) ? 1.0f : 0.0f;
    float mx1 = (xs1 >= -1.0f && xs1 <= (float)WW) ? 1.0f : 0.0f;
    float xc0 = fminf(fmaxf(xs0, 0.0f), (float)(WW - 1));
    float xc1 = fminf(fmaxf(xs1, 0.0f), (float)(WW - 1));
    int x00 = (int)floorf(xc0);
    int x01 = (int)floorf(xc1);
    int x10 = min(x00 + 1, WW - 1);
    int x11 = min(x01 + 1, WW - 1);
    float lx0 = xc0 - (float)x00, hx0 = 1.0f - lx0;
    float lx1 = xc1 - (float)x01, hx1 = 1.0f - lx1;

    int xa  = x00 & ~3;
    int o00 = x00 - xa;                    // 0..3
    int o01 = x10 - xa;                    // 0..4
    int o10 = x01 - xa;                    // 0..5
    int o11 = x11 - xa;                    // 0..6
    bool need_hi = o11 > 3;                // implies xa <= 72; hi window in-bounds

    float c0 = 0.25f * mx0 * hx0, c1 = 0.25f * mx0 * lx0;
    float c2 = 0.25f * mx1 * hx1, c3 = 0.25f * mx1 * lx1;
    float Wx[8];
    #pragma unroll
    for (int k = 0; k < 8; ++k) {
        float w = (o00 == k) ? c0 : 0.0f;
        w += (o01 == k) ? c1 : 0.0f;
        w += (o10 == k) ? c2 : 0.0f;
        w += (o11 == k) ? c3 : 0.0f;
        Wx[k] = w;
    }

    // ---- y geometry -> 4-wide row weight vector Wy over rows yb..yb+3 ----
    float ybase = ry1 + (float)ph * bin_h;

    float ys0 = ybase + 0.25f * bin_h;
    float ys1 = ybase + 0.75f * bin_h;
    float my0 = (ys0 >= -1.0f && ys0 <= (float)HH) ? 1.0f : 0.0f;
    float my1 = (ys1 >= -1.0f && ys1 <= (float)HH) ? 1.0f : 0.0f;
    float yc0 = fminf(fmaxf(ys0, 0.0f), (float)(HH - 1));
    float yc1 = fminf(fmaxf(ys1, 0.0f), (float)(HH - 1));
    int y00 = (int)floorf(yc0);            // = yb (min row; yc1 >= yc0)
    int y01 = (int)floorf(yc1);
    int y10 = min(y00 + 1, HH - 1);
    int y11 = min(y01 + 1, HH - 1);
    float ly0 = yc0 - (float)y00;
    float ly1 = yc1 - (float)y01;
    float wA0 = my0 * (1.0f - ly0), wB0 = my0 * ly0;
    float wA1 = my1 * (1.0f - ly1), wB1 = my1 * ly1;

    int yb = y00;
    int k0 = 0;                            // y00 - yb
    int k1 = y10 - yb;                     // 0..1
    int k2 = y01 - yb;                     // 0..2
    int k3 = y11 - yb;                     // 0..3

    float Wy[4];
    #pragma unroll
    for (int k = 0; k < 4; ++k) {
        float w = (k0 == k) ? wA0 : 0.0f;
        w += (k1 == k) ? wB0 : 0.0f;
        w += (k2 == k) ? wA1 : 0.0f;
        w += (k3 == k) ? wB1 : 0.0f;
        Wy[k] = w;
    }

    const float* base0 = f + yb * WW + xa;
    float4 zero = make_float4(0.f, 0.f, 0.f, 0.f);
    float acc;

    // ---- round 1: rows yb, yb+1 (always needed in practice) ----
    {
        float4 Alo = __ldg((const float4*)base0);
        float4 Blo = __ldg((const float4*)(base0 + WW));
        float4 Ahi = zero, Bhi = zero;
        if (need_hi) {
            Ahi = __ldg((const float4*)(base0 + 4));
            Bhi = __ldg((const float4*)(base0 + WW + 4));
        }
        acc = Wy[0] * dot8(Alo, Ahi, Wx);
        acc = fmaf(Wy[1], dot8(Blo, Bhi, Wx), acc);
    }
    // ---- round 2: rows yb+2, yb+3, only when weighted ----
    if (Wy[2] != 0.0f) {
        const float* base2 = base0 + 2 * WW;
        float4 Alo = __ldg((const float4*)base2);
        float4 Ahi = zero;
        float4 Blo = zero, Bhi = zero;
        bool r3 = (Wy[3] != 0.0f);
        if (r3) Blo = __ldg((const float4*)(base2 + WW));
        if (need_hi) {
            Ahi = __ldg((const float4*)(base2 + 4));
            if (r3) Bhi = __ldg((const float4*)(base2 + WW + 4));
        }
        acc = fmaf(Wy[2], dot8(Alo, Ahi, Wx), acc);
        acc = fmaf(Wy[3], dot8(Blo, Bhi, Wx), acc);
    }

    out[tid] = acc;
}

extern "C" void kernel_launch(void* const* d_in, const int* in_sizes, int n_in,
                              void* d_out, int out_size)
{
    const float* feat = (const float*)d_in[0];
    const float* rois = (const float*)d_in[1];
    float* out = (float*)d_out;

    int N = in_sizes[1] / 5;            // 512 rois
    int total = N * 16 * PH * PW;       // 401408 outputs

    int threads = 256;
    int blocks = (total + threads - 1) / threads;
    psroi_align_kernel<<<blocks, threads>>>(feat, rois, out, total);
}

// round 16
// speedup vs baseline: 1.3467x; 1.1206x over previous
#include <cuda_runtime.h>

// PSRoIAlign: feat [B=4, C=784, H=80, W=80] f32, rois [N=512, 5] f32
// out [N, 16, 7, 7] f32. Channel of output element = r = co*49 + ph*7 + pw.
//
// R16 = R14 row-dedup (4 bilinear rows of both sy samples collapse to <=4
// distinct rows yb..yb+3, separable y-weight vector Wy) with FLAT control
// flow: phase-B rows individually predicated (@P LDG, no nested divergent
// blocks). R5 skeleton otherwise: two phases, <=4 live float4, no smem,
// lb(256,5). Expected ~5.0 LDG.128/thread vs R5's ~6.2.

#define PH 7
#define PW 7
#define HH 80
#define WW 80
#define CC 784

__device__ __forceinline__ float dot8(float4 lo, float4 hi, const float* W) {
    float s = lo.x * W[0];
    s = fmaf(lo.y, W[1], s);
    s = fmaf(lo.z, W[2], s);
    s = fmaf(lo.w, W[3], s);
    s = fmaf(hi.x, W[4], s);
    s = fmaf(hi.y, W[5], s);
    s = fmaf(hi.z, W[6], s);
    s = fmaf(hi.w, W[7], s);
    return s;
}

__global__ void __launch_bounds__(256, 5)
psroi_align_kernel(const float* __restrict__ feat,
                   const float* __restrict__ rois,
                   float* __restrict__ out,
                   int total)
{
    int tid = blockIdx.x * blockDim.x + threadIdx.x;
    if (tid >= total) return;

    int n = tid / (PH * PW * 16);
    int r = tid - n * (PH * PW * 16);      // channel index
    int pw = r % PW;
    int ph = (r / PW) % PH;

    const float* roi = rois + n * 5;
    int   b   = (int)roi[0];
    float rx1 = roi[1] * (float)WW;
    float ry1 = roi[2] * (float)HH;
    float rx2 = roi[3] * (float)WW;
    float ry2 = roi[4] * (float)HH;

    float roi_h = fmaxf(ry2 - ry1, 0.1f);
    float roi_w = fmaxf(rx2 - rx1, 0.1f);
    float bin_h = roi_h * (1.0f / PH);
    float bin_w = roi_w * (1.0f / PW);

    const float* __restrict__ f = feat + ((size_t)b * CC + (size_t)r) * (HH * WW);

    // ---- x geometry -> 8-wide tap weight vector Wx (masks + 1/4 folded) ----
    float xs0 = rx1 + (float)pw * bin_w + 0.25f * bin_w;
    float xs1 = xs0 + 0.5f * bin_w;
    float mx0 = (xs0 >= -1.0f && xs0 <= (float)WW) ? 1.0f : 0.0f;
    float mx1 = (xs1 >= -1.0f && xs1 <= (float)WW) ? 1.0f : 0.0f;
    float xc0 = fminf(fmaxf(xs0, 0.0f), (float)(WW - 1));
    float xc1 = fminf(fmaxf(xs1, 0.0f), (float)(WW - 1));
    int x00 = (int)floorf(xc0);
    int x01 = (int)floorf(xc1);
    int x10 = min(x00 + 1, WW - 1);
    int x11 = min(x01 + 1, WW - 1);
    float lx0 = xc0 - (float)x00, hx0 = 1.0f - lx0;
    float lx1 = xc1 - (float)x01, hx1 = 1.0f - lx1;

    int xa  = x00 & ~3;
    int o00 = x00 - xa;                    // 0..3
    int o01 = x10 - xa;                    // 0..4
    int o10 = x01 - xa;                    // 0..5
    int o11 = x11 - xa;                    // 0..6
    bool need_hi = o11 > 3;                // implies xa <= 72; hi window in-bounds

    float c0 = 0.25f * mx0 * hx0, c1 = 0.25f * mx0 * lx0;
    float c2 = 0.25f * mx1 * hx1, c3 = 0.25f * mx1 * lx1;
    float Wx[8];
    #pragma unroll
    for (int k = 0; k < 8; ++k) {
        float w = (o00 == k) ? c0 : 0.0f;
        w += (o01 == k) ? c1 : 0.0f;
        w += (o10 == k) ? c2 : 0.0f;
        w += (o11 == k) ? c3 : 0.0f;
        Wx[k] = w;
    }

    // ---- y geometry -> 4-wide row weight vector Wy over rows yb..yb+3 ----
    float ybase = ry1 + (float)ph * bin_h;
    float ys0 = ybase + 0.25f * bin_h;
    float ys1 = ybase + 0.75f * bin_h;
    float my0 = (ys0 >= -1.0f && ys0 <= (float)HH) ? 1.0f : 0.0f;
    float my1 = (ys1 >= -1.0f && ys1 <= (float)HH) ? 1.0f : 0.0f;
    float yc0 = fminf(fmaxf(ys0, 0.0f), (float)(HH - 1));
    float yc1 = fminf(fmaxf(ys1, 0.0f), (float)(HH - 1));
    int y00 = (int)floorf(yc0);            // = yb (yc1 >= yc0)
    int y01 = (int)floorf(yc1);
    int y10 = min(y00 + 1, HH - 1);
    int y11 = min(y01 + 1, HH - 1);
    float ly0 = yc0 - (float)y00;
    float ly1 = yc1 - (float)y01;
    float wA0 = my0 * (1.0f - ly0), wB0 = my0 * ly0;
    float wA1 = my1 * (1.0f - ly1), wB1 = my1 * ly1;

    int yb = y00;
    int k1 = y10 - yb;                     // 0..1
    int k2 = y01 - yb;                     // 0..2
    int k3 = y11 - yb;                     // 0..3

    float Wy0 = wA0 + ((k1 == 0) ? wB0 : 0.0f)
                    + ((k2 == 0) ? wA1 : 0.0f) + ((k3 == 0) ? wB1 : 0.0f);
    float Wy1 = ((k1 == 1) ? wB0 : 0.0f)
              + ((k2 == 1) ? wA1 : 0.0f) + ((k3 == 1) ? wB1 : 0.0f);
    float Wy2 = ((k2 == 2) ? wA1 : 0.0f) + ((k3 == 2) ? wB1 : 0.0f);
    float Wy3 = ((k3 == 3) ? wB1 : 0.0f);

    const float* base0 = f + yb * WW + xa;
    float4 zero = make_float4(0.f, 0.f, 0.f, 0.f);

    // Flat predicates (computed once; no nesting)
    bool p2  = Wy2 != 0.0f;
    bool p3  = Wy3 != 0.0f;
    bool p2h = p2 && need_hi;
    bool p3h = p3 && need_hi;

    float acc;

    // ---- phase A: rows yb, yb+1 ----
    {
        float4 Alo = __ldg((const float4*)base0);
        float4 Blo = __ldg((const float4*)(base0 + WW));
        float4 Ahi = zero, Bhi = zero;
        if (need_hi) {
            Ahi = __ldg((const float4*)(base0 + 4));
            Bhi = __ldg((const float4*)(base0 + WW + 4));
        }
        acc = Wy0 * dot8(Alo, Ahi, Wx);
        acc = fmaf(Wy1, dot8(Blo, Bhi, Wx), acc);
    }
    // ---- phase B: rows yb+2, yb+3, individually predicated (flat) ----
    {
        const float* base2 = base0 + 2 * WW;
        float4 Clo = zero, Dlo = zero, Chi = zero, Dhi = zero;
        if (p2)  Clo = __ldg((const float4*)base2);
        if (p3)  Dlo = __ldg((const float4*)(base2 + WW));
        if (p2h) Chi = __ldg((const float4*)(base2 + 4));
        if (p3h) Dhi = __ldg((const float4*)(base2 + WW + 4));
        acc = fmaf(Wy2, dot8(Clo, Chi, Wx), acc);
        acc = fmaf(Wy3, dot8(Dlo, Dhi, Wx), acc);
    }

    out[tid] = acc;
}

extern "C" void kernel_launch(void* const* d_in, const int* in_sizes, int n_in,
                              void* d_out, int out_size)
{
    const float* feat = (const float*)d_in[0];
    const float* rois = (const float*)d_in[1];
    float* out = (float*)d_out;

    int N = in_sizes[1] / 5;            // 512 rois
    int total = N * 16 * PH * PW;       // 401408 outputs

    int threads = 256;
    int blocks = (total + threads - 1) / threads;
    psroi_align_kernel<<<blocks, threads>>>(feat, rois, out, total);
}